// round 11
// baseline (speedup 1.0000x reference)
#include <cuda_runtime.h>
#include <cuda_fp16.h>
#include <cstdint>

// ---------------------------------------------------------------------------
// MSAttention: einsum 'bkhwlm,bkhwlnf->bkhwlf' factorizes as
// (sum_m A)*(sum_n V) = 1 * sum_n V  =>  attention is dead code. Output is a
// sum of V-projections of (block-sum) pooled inputs:
//   out0 = Wvkid0*pool2(x1) + up4( Wvpeer0*pool4(x0) )
//   out1 = Wvkid1*pool2(x2) + up2( Wvpeer1*pool2(x1) + Wvpar1*x0 )
//   out2 =                    up2( Wvpeer2*pool2(x2) + Wvpar2*x1 )
// Wv* = rows [256,512) of the kv weights.
//
// mma.sync m16n8k16 fp16 / fp32 acc; operands pre-staged chunk-planar and
// pre-swizzled so each 8KB tile loads with one cp.async.bulk. ONE GEMM launch
// of exactly 296 CTAs (one full wave at occ 2): C-producing CTAs signal a
// counter; consumers wait only before their gather-add epilogue. 26 CTAs run
// TWO fine tiles back-to-back, stashing the first tile's accumulators to a
// gmem scratch, so the second mainloop overlaps the producers' K=512 work
// instead of spinning (kills the wave-2 tail).
// ---------------------------------------------------------------------------

// ---- staged operands ----
__device__ __align__(1024) __half g_P0[128 * 256];
__device__ __align__(1024) __half g_Pa[2048 * 256];
__device__ __align__(1024) __half g_Pb[8192 * 256];
__device__ __align__(1024) __half g_W[7 * 65536];
__device__ float g_C0[128 * 256];
__device__ float g_C1[2048 * 256];
__device__ float g_stash[26 * 16384];
__device__ int g_done;

// ---------------------------------------------------------------------------
// PTX helpers (baseline sm_90 features only)
// ---------------------------------------------------------------------------
__device__ __forceinline__ uint32_t smem_to_u32(const void* p) {
    uint32_t a;
    asm("{ .reg .u64 t; cvta.to.shared.u64 t, %1; cvt.u32.u64 %0, t; }" : "=r"(a) : "l"(p));
    return a;
}
__device__ __forceinline__ void bulk_cp(uint32_t smem, const void* gmem, uint32_t bytes,
                                        uint32_t mbar) {
    asm volatile(
        "cp.async.bulk.shared::cluster.global.mbarrier::complete_tx::bytes [%0], [%1], %2, [%3];"
        :: "r"(smem), "l"(gmem), "r"(bytes), "r"(mbar) : "memory");
}
#define MBARRIER_INIT(mbar, cnt) \
    asm volatile("mbarrier.init.shared.b64 [%0], %1;" :: "r"((uint32_t)(mbar)), "r"((uint32_t)(cnt)) : "memory")
#define MBARRIER_EXPECT_TX(mbar, tx) \
    asm volatile("mbarrier.arrive.expect_tx.shared.b64 _, [%0], %1;" :: "r"((uint32_t)(mbar)), "r"((uint32_t)(tx)) : "memory")
#define MBARRIER_WAIT_PARITY(mbar, par) do {                                      \
    uint32_t _m = (uint32_t)(mbar); uint32_t _p = (uint32_t)(par); uint32_t _d;   \
    asm volatile("{\n\t.reg .pred p;\n\t"                                         \
        "mbarrier.try_wait.parity.acquire.cta.shared::cta.b64 p, [%1], %2;\n\t"   \
        "selp.b32 %0, 1, 0, p;\n\t}" : "=r"(_d) : "r"(_m), "r"(_p) : "memory");   \
    if (!_d) {                                                                     \
        asm volatile("{\n\t.reg .pred P1;\n\t"                                    \
            "WL_%=:\n\t"                                                          \
            "mbarrier.try_wait.parity.acquire.cta.shared::cta.b64 P1, [%0], %1, 0x989680;\n\t" \
            "@P1 bra.uni WD_%=;\n\t"                                              \
            "bra.uni WL_%=;\n\t"                                                  \
            "WD_%=:\n\t}" :: "r"(_m), "r"(_p) : "memory");                        \
    }                                                                              \
} while (0)

__device__ __forceinline__ void ldsm4(uint32_t* r, uint32_t addr) {
    asm volatile("ldmatrix.sync.aligned.m8n8.x4.shared.b16 {%0,%1,%2,%3}, [%4];"
                 : "=r"(r[0]), "=r"(r[1]), "=r"(r[2]), "=r"(r[3]) : "r"(addr));
}
__device__ __forceinline__ void ldsm2(uint32_t* r, uint32_t addr) {
    asm volatile("ldmatrix.sync.aligned.m8n8.x2.shared.b16 {%0,%1}, [%2];"
                 : "=r"(r[0]), "=r"(r[1]) : "r"(addr));
}
__device__ __forceinline__ void mma16816(float* d, const uint32_t* a, const uint32_t* b) {
    asm volatile(
        "mma.sync.aligned.m16n8k16.row.col.f32.f16.f16.f32 "
        "{%0,%1,%2,%3}, {%4,%5,%6,%7}, {%8,%9}, {%0,%1,%2,%3};"
        : "+f"(d[0]), "+f"(d[1]), "+f"(d[2]), "+f"(d[3])
        : "r"(a[0]), "r"(a[1]), "r"(a[2]), "r"(a[3]), "r"(b[0]), "r"(b[1]));
}
__device__ __forceinline__ void sts128(uint32_t addr, uint4 v) {
    asm volatile("st.shared.v4.b32 [%0], {%1,%2,%3,%4};"
                 :: "r"(addr), "r"(v.x), "r"(v.y), "r"(v.z), "r"(v.w) : "memory");
}

// slot byte-offset inside a chunk plane for (row r, 16B-slot t)
__device__ __forceinline__ uint32_t plane_off(int r, int t) {
    return (uint32_t)((r >> 1) * 128 + (((((r & 1) << 2) | t) ^ ((r >> 1) & 7)) << 4));
}

// ---------------------------------------------------------------------------
// Prep: pools + fp32->fp16, written chunk-planar pre-swizzled.
// ---------------------------------------------------------------------------
#define S0 (128 * 32)      // P0 slots
#define S1 (2048 * 32)     // Pa
#define S2 (8192 * 32)     // Pb
#define SW (7 * 256 * 32)  // weights
#define PREP_TOTAL (S0 + S1 + S2 + SW)

struct PrepArgs {
    const float* x0; const float* x1; const float* x2;
    const float* w[7];
};

__device__ __forceinline__ uint4 pack8(float4 a, float4 b) {
    __half2 h0 = __floats2half2_rn(a.x, a.y);
    __half2 h1 = __floats2half2_rn(a.z, a.w);
    __half2 h2 = __floats2half2_rn(b.x, b.y);
    __half2 h3 = __floats2half2_rn(b.z, b.w);
    uint4 u;
    u.x = *(uint32_t*)&h0; u.y = *(uint32_t*)&h1;
    u.z = *(uint32_t*)&h2; u.w = *(uint32_t*)&h3;
    return u;
}

__device__ __forceinline__ void prep_pool(const float* in, __half* dst, int R, int Hc,
                                          int f, int i) {
    const int t = i & 3;
    const int r = (i >> 2) % R;
    const int c = (i >> 2) / R;
    int q = r % Hc;
    int tmp = r / Hc;
    int p = tmp % Hc;
    int b = tmp / Hc;
    const int c8 = c * 8 + t * 2;
    const int Win = Hc * f;
    const float4* in4 = (const float4*)in;
    float4 s0 = make_float4(0.f, 0.f, 0.f, 0.f);
    float4 s1 = make_float4(0.f, 0.f, 0.f, 0.f);
    for (int dy = 0; dy < f; ++dy)
        for (int dx = 0; dx < f; ++dx) {
            const float4* pp = &in4[(size_t)((b * Hc * f + p * f + dy) * Win + q * f + dx) * 64 + c8];
            float4 v0 = pp[0], v1 = pp[1];
            s0.x += v0.x; s0.y += v0.y; s0.z += v0.z; s0.w += v0.w;
            s1.x += v1.x; s1.y += v1.y; s1.z += v1.z; s1.w += v1.w;
        }
    __half* d = dst + (size_t)c * R * 32 + (plane_off(r, t) >> 1);
    *(uint4*)d = pack8(s0, s1);
}

__global__ void prep_kernel(PrepArgs pa) {
    if (blockIdx.x == 0 && threadIdx.x == 0) g_done = 0;
    int i = blockIdx.x * blockDim.x + threadIdx.x;
    const int VOFF = 256 * 256;
    if (i < S0) {
        prep_pool(pa.x0, g_P0, 128, 4, 4, i);
    } else if ((i -= S0) < S1) {
        prep_pool(pa.x1, g_Pa, 2048, 16, 2, i);
    } else if ((i -= S1) < S2) {
        prep_pool(pa.x2, g_Pb, 8192, 32, 2, i);
    } else if ((i -= S2) < SW) {
        const int mat = i >> 13;
        const int rem = i & 8191;
        const int c = rem >> 10;
        const int r = (rem >> 2) & 255;
        const int t = rem & 3;
        const float* src = pa.w[mat] + VOFF + r * 256 + c * 32 + t * 8;
        float4 v0 = ((const float4*)src)[0];
        float4 v1 = ((const float4*)src)[1];
        __half* p = g_W + ((size_t)mat << 16) + (size_t)c * 256 * 32 + (plane_off(r, t) >> 1);
        *(uint4*)p = pack8(v0, v1);
    }
}

// ---------------------------------------------------------------------------
// GEMM: BM=128, BN=128, BK=32, 8 warps, 4-stage bulk-copy mbarrier pipeline.
// K=512 jobs: chunks 8..15 take A from fp32 gmem (A2f) via LDG+swizzled STS.
// mode 0: plain; 1: scatter-up by F; 2: gather-add Cadd[coarse(m)].
// dep 0 none; 1 producer (signal g_done); 2 consumer (wait before epilogue).
// ---------------------------------------------------------------------------
struct TCJob {
    const __half *A1, *W1, *W2;
    const float* A2f;
    float* out;
    const float* Cadd;
    int aplane;   // bytes per A chunk plane (= R*64)
    int tile_end, Hc, Wc, F, mode, dep;
};
struct TCJobs { TCJob j[5]; int njobs; int nprod; };

#define STG 16384                  // stage bytes: A 8KB + B 8KB
#define SMEM_TOTAL (4 * STG)       // 65536
#define PAIR_BASE 270              // tiles >= PAIR_BASE run 2-per-CTA
#define GRID_CTAS 296

__device__ __forceinline__ void tc_epilogue(const TCJob& jb, int m0, int n0,
                                            int lid, int wm, int wn,
                                            const float (*acc)[4][4]) {
    const int g = lid >> 2;
    const int tg = lid & 3;
#pragma unroll
    for (int mi = 0; mi < 4; ++mi) {
#pragma unroll
        for (int half = 0; half < 2; ++half) {
            const int rm = m0 + wm * 64 + mi * 16 + g + half * 8;
            if (jb.mode == 0) {
                float* dst = jb.out + (size_t)rm * 256;
#pragma unroll
                for (int ni = 0; ni < 4; ++ni) {
                    const int cn = n0 + wn * 32 + ni * 8 + tg * 2;
                    *(float2*)(dst + cn) = make_float2(acc[mi][ni][half * 2],
                                                       acc[mi][ni][half * 2 + 1]);
                }
            } else if (jb.mode == 1) {
                const int HW = jb.Hc * jb.Wc;
                const int b = rm / HW;
                const int rem = rm - b * HW;
                const int h = rem / jb.Wc;
                const int w = rem - h * jb.Wc;
                const int Wf = jb.Wc * jb.F;
                for (int dy = 0; dy < jb.F; ++dy)
                    for (int dx = 0; dx < jb.F; ++dx) {
                        size_t fm = (size_t)(b * jb.Hc * jb.F + h * jb.F + dy) * Wf
                                    + (w * jb.F + dx);
                        float* dst = jb.out + fm * 256;
#pragma unroll
                        for (int ni = 0; ni < 4; ++ni) {
                            const int cn = n0 + wn * 32 + ni * 8 + tg * 2;
                            *(float2*)(dst + cn) = make_float2(acc[mi][ni][half * 2],
                                                               acc[mi][ni][half * 2 + 1]);
                        }
                    }
            } else {
                const int Wf = jb.Wc * jb.F;
                const int HWf = jb.Hc * jb.F * Wf;
                const int b = rm / HWf;
                const int rem = rm - b * HWf;
                const int h = rem / Wf;
                const int w = rem - h * Wf;
                const int crow = (b * jb.Hc + h / jb.F) * jb.Wc + (w / jb.F);
                const float* csrc = jb.Cadd + (size_t)crow * 256;
                float* dst = jb.out + (size_t)rm * 256;
#pragma unroll
                for (int ni = 0; ni < 4; ++ni) {
                    const int cn = n0 + wn * 32 + ni * 8 + tg * 2;
                    float2 cv = *(const float2*)(csrc + cn);
                    *(float2*)(dst + cn) = make_float2(acc[mi][ni][half * 2] + cv.x,
                                                       acc[mi][ni][half * 2 + 1] + cv.y);
                }
            }
        }
    }
}

__global__ void __launch_bounds__(256, 2)
gemm_tc(TCJobs jobs) {
    extern __shared__ char smem[];
    __shared__ __align__(8) unsigned long long mbars[4];
    const uint32_t sb = smem_to_u32(smem);
    const uint32_t mb = smem_to_u32(mbars);
    const int tid = threadIdx.x;
    const int lid = tid & 31;
    const int wid = tid >> 5;
    const int wm = wid >> 2;       // 0..1
    const int wn = wid & 3;        // 0..3

    const int bt = blockIdx.x;
    int t0, nrep;
    if (bt < PAIR_BASE) { t0 = bt; nrep = 1; }
    else { t0 = PAIR_BASE + (bt - PAIR_BASE) * 2; nrep = 2; }

    if (tid == 0) {
#pragma unroll
        for (int s = 0; s < 4; ++s) MBARRIER_INIT(mb + 8 * s, 1);
    }
    __syncthreads();

    // per-thread ldmatrix address precompute (tile-invariant)
    const int rA0 = wm * 64 + (lid & 15);
    const int hiA = lid >> 4;
    const uint32_t aBase = (rA0 >> 1) * 128;
    const int xvA = (rA0 >> 1) & 7;
    const int pbA = (rA0 & 1) << 2;
    const uint32_t soA0 = (uint32_t)(((pbA | hiA) ^ xvA) << 4);
    const uint32_t soA1 = (uint32_t)(((pbA | (2 + hiA)) ^ xvA) << 4);

    const int l16 = lid & 15;
    const int rB0 = wn * 32 + (l16 & 7);
    const int hiB = l16 >> 3;
    const uint32_t bBase = (rB0 >> 1) * 128;
    const int xvB = (rB0 >> 1) & 7;
    const int pbB = (rB0 & 1) << 2;
    const uint32_t soB00 = (uint32_t)(((pbB | hiB) ^ xvB) << 4);
    const uint32_t soB01 = (uint32_t)(((pbB | hiB) ^ xvB ^ 4) << 4);
    const uint32_t soB10 = (uint32_t)(((pbB | (2 + hiB)) ^ xvB) << 4);
    const uint32_t soB11 = (uint32_t)(((pbB | (2 + hiB)) ^ xvB ^ 4) << 4);

    // fp32 A path indices (thread covers one row, two 16B slots)
    const int fr = tid >> 1;
    const int ft = (tid & 1) * 2;

    int gbase = 0;          // absolute chunk counter (stage/parity bookkeeping)
    int m00 = 0, n00 = 0;   // first tile's coords for the paired-epilogue path

    for (int rep = 0; rep < nrep; ++rep) {
        const int tile = t0 + rep;
        int ji = 0;
#pragma unroll
        for (int t = 0; t < 4; ++t)
            if (t + 1 < jobs.njobs && tile >= jobs.j[t].tile_end) ji = t + 1;
        const TCJob jb = jobs.j[ji];
        const int local = tile - (ji == 0 ? 0 : jobs.j[ji - 1].tile_end);
        const int m0 = (local >> 1) * 128;
        const int n0 = (local & 1) * 128;
        const int nch = jb.W2 ? 16 : 8;

        float acc[4][4][4];
#pragma unroll
        for (int a = 0; a < 4; ++a)
#pragma unroll
            for (int b = 0; b < 4; ++b)
#pragma unroll
                for (int c = 0; c < 4; ++c) acc[a][b][c] = 0.f;

        // issue local chunk c into stage (gbase+c)&3
        auto issue = [&](int c) {
            const int s = (gbase + c) & 3;
            const uint32_t stg = sb + s * STG;
            const bool bulkA = (c < 8);
            MBARRIER_EXPECT_TX(mb + 8 * s, bulkA ? 16384u : 8192u);
            const char* wsrc = (const char*)((c < 8) ? jb.W1 : jb.W2) + (c & 7) * 16384 + n0 * 64;
            bulk_cp(stg + 8192, wsrc, 8192, mb + 8 * s);
            if (bulkA) {
                const char* asrc = (const char*)jb.A1 + (size_t)c * jb.aplane + (size_t)m0 * 64;
                bulk_cp(stg, asrc, 8192, mb + 8 * s);
            }
        };

        if (tid == 0) { issue(0); issue(1); issue(2); }

        float4 st[4];

#pragma unroll 1
        for (int c = 0; c < nch; ++c) {
            const int ac = gbase + c;
            const int s = ac & 3;
            MBARRIER_WAIT_PARITY(mb + 8 * s, (ac >> 2) & 1);

            const int c3 = c + 3;
            const bool ld2 = (c3 < nch) && (c3 >= 8);
            if (ld2) {
                const float* g = jb.A2f + (size_t)(m0 + fr) * 256 + (c3 & 7) * 32 + ft * 8;
                st[0] = ((const float4*)g)[0];
                st[1] = ((const float4*)g)[1];
                st[2] = ((const float4*)g)[2];
                st[3] = ((const float4*)g)[3];
            }

            const uint32_t sA = sb + s * STG;
            const uint32_t sB = sA + 8192;
#pragma unroll
            for (int ks = 0; ks < 2; ++ks) {
                uint32_t b[4][2];
                const uint32_t sbk0 = ks ? soB10 : soB00;
                const uint32_t sbk1 = ks ? soB11 : soB01;
#pragma unroll
                for (int ni = 0; ni < 4; ++ni)
                    ldsm2(b[ni], sB + bBase + ni * 512 + ((ni & 1) ? sbk1 : sbk0));
                const uint32_t sak = ks ? soA1 : soA0;
#pragma unroll
                for (int mi = 0; mi < 4; ++mi) {
                    uint32_t a[4];
                    ldsm4(a, sA + aBase + mi * 1024 + sak);
#pragma unroll
                    for (int ni = 0; ni < 4; ++ni)
                        mma16816(acc[mi][ni], a, b[ni]);
                }
            }

            if (ld2) {
                const uint32_t stg = sb + ((gbase + c3) & 3) * STG + (fr >> 1) * 128;
                const int pb = (fr & 1) << 2;
                const int xv = (fr >> 1) & 7;
                sts128(stg + (((pb | ft) ^ xv) << 4), pack8(st[0], st[1]));
                sts128(stg + (((pb | (ft + 1)) ^ xv) << 4), pack8(st[2], st[3]));
            }
            __syncthreads();
            if (c3 < nch && tid == 0) issue(c3);
        }
        gbase += nch;

        if (nrep == 2 && rep == 0) {
            // stash tile-1 accumulators; epilogue deferred to rep 1
            float* sp = g_stash + (size_t)(bt - PAIR_BASE) * 16384 + tid;
            const float* af = (const float*)acc;
#pragma unroll
            for (int j = 0; j < 64; ++j) sp[j * 256] = af[j];
            m00 = m0; n00 = n0;
            continue;
        }

        // consumers: wait for all C producers before gather-add epilogues
        if (jb.dep == 2) {
            if (tid == 0) {
                while (atomicAdd(&g_done, 0) < jobs.nprod) { }
            }
            __syncthreads();
        }

        tc_epilogue(jb, m0, n0, lid, wm, wn, acc);

        if (rep == 1) {
            // unstash and finish tile 1 (same job as tile 2)
            float acc0[4][4][4];
            float* af0 = (float*)acc0;
            const float* sp = g_stash + (size_t)(bt - PAIR_BASE) * 16384 + tid;
#pragma unroll
            for (int j = 0; j < 64; ++j) af0[j] = sp[j * 256];
            tc_epilogue(jb, m00, n00, lid, wm, wn, acc0);
        }

        // producers: make C visible, then signal
        if (jb.dep == 1) {
            __threadfence();
            __syncthreads();
            if (tid == 0) atomicAdd(&g_done, 1);
        }
    }
}

// ---------------------------------------------------------------------------
// Launch
// ---------------------------------------------------------------------------
extern "C" void kernel_launch(void* const* d_in, const int* in_sizes, int n_in,
                              void* d_out, int out_size) {
    (void)n_in; (void)out_size;

    const float* x0 = (const float*)d_in[0];   // [8,16,16,256]
    const float* x1 = (const float*)d_in[1];   // [8,32,32,256]
    const float* x2 = (const float*)d_in[2];   // [8,64,64,256]

    // setup_inputs() builds the dict INTERLEAVED (qpeer_w0, kvpeer_w0, ...).
    const bool inter = (in_sizes[4] == 2 * 256 * 256);
    const float* kvpeer0 = (const float*)d_in[inter ? 4  : 6];
    const float* kvpeer1 = (const float*)d_in[inter ? 6  : 7];
    const float* kvpeer2 = (const float*)d_in[inter ? 8  : 8];
    const float* kvpar1  = (const float*)d_in[inter ? 10 : 11];
    const float* kvpar2  = (const float*)d_in[inter ? 12 : 12];
    const float* kvkid0  = (const float*)d_in[inter ? 14 : 15];
    const float* kvkid1  = (const float*)d_in[inter ? 16 : 16];

    __half *P0, *Pa, *Pb, *W;
    float *C0, *C1;
    cudaGetSymbolAddress((void**)&P0, g_P0);
    cudaGetSymbolAddress((void**)&Pa, g_Pa);
    cudaGetSymbolAddress((void**)&Pb, g_Pb);
    cudaGetSymbolAddress((void**)&W, g_W);
    cudaGetSymbolAddress((void**)&C0, g_C0);
    cudaGetSymbolAddress((void**)&C1, g_C1);

    float* out0 = (float*)d_out;                 // 8*16*16*256
    float* out1 = out0 + 8 * 16 * 16 * 256;      // 8*32*32*256
    float* out2 = out1 + 8 * 32 * 32 * 256;      // 8*64*64*256

    cudaFuncSetAttribute(gemm_tc, cudaFuncAttributeMaxDynamicSharedMemorySize, SMEM_TOTAL);

    // 1) prep (also resets g_done)
    PrepArgs pa;
    pa.x0 = x0; pa.x1 = x1; pa.x2 = x2;
    pa.w[0] = kvpeer0; pa.w[1] = kvpeer1; pa.w[2] = kvpeer2;
    pa.w[3] = kvpar1;  pa.w[4] = kvpar2;  pa.w[5] = kvkid0;  pa.w[6] = kvkid1;
    prep_kernel<<<(PREP_TOTAL + 255) / 256, 256>>>(pa);

    __half* W0 = W;             // peer0
    __half* W1 = W + 65536;     // peer1
    __half* W2 = W + 131072;    // peer2
    __half* W3 = W + 196608;    // par1
    __half* W4 = W + 262144;    // par2
    __half* W5 = W + 327680;    // kid0
    __half* W6 = W + 393216;    // kid1

    // 2) single merged GEMM launch, exactly one wave (296 CTAs, 322 tiles;
    //    tiles 270..321 run paired on CTAs 270..295). Producers = blocks 0..33.
    TCJobs tj;
    tj.njobs = 5;
    tj.nprod = 34;
    //        A1  W1  W2      A2f  out   Cadd    aplane    end  Hc  Wc F  mode dep
    tj.j[0] = { P0, W0, nullptr, nullptr, C0,   nullptr, 128 * 64,  2,   0,  0, 0, 0, 1 };
    tj.j[1] = { Pa, W1, W3,      x0,      C1,   nullptr, 2048 * 64, 34,  0,  0, 0, 0, 1 };
    tj.j[2] = { Pb, W2, W4,      x1,      out2, nullptr, 8192 * 64, 162, 32, 32, 2, 1, 0 };
    tj.j[3] = { Pa, W5, nullptr, nullptr, out0, C0,      2048 * 64, 194, 4,  4,  4, 2, 2 };
    tj.j[4] = { Pb, W6, nullptr, nullptr, out1, C1,      8192 * 64, 322, 16, 16, 2, 2, 2 };
    gemm_tc<<<GRID_CTAS, 256, SMEM_TOTAL>>>(tj);
}

// round 12
// speedup vs baseline: 1.0853x; 1.0853x over previous
#include <cuda_runtime.h>
#include <cuda_fp16.h>
#include <cstdint>

// ---------------------------------------------------------------------------
// MSAttention: einsum 'bkhwlm,bkhwlnf->bkhwlf' factorizes as
// (sum_m A)*(sum_n V) = 1 * sum_n V  =>  attention is dead code. Output is a
// sum of V-projections of (block-sum) pooled inputs:
//   out0 = Wvkid0*pool2(x1) + up4( Wvpeer0*pool4(x0) )
//   out1 = Wvkid1*pool2(x2) + up2( Wvpeer1*pool2(x1) + Wvpar1*x0 )
//   out2 =                    up2( Wvpeer2*pool2(x2) + Wvpar2*x1 )
// Wv* = rows [256,512) of the kv weights.
//
// mma.sync m16n8k16 fp16 / fp32 acc, operands pre-staged chunk-planar and
// pre-swizzled so each 8KB tile loads with one cp.async.bulk. ONE GEMM launch
// (322 CTAs; HW scheduler absorbs the small wave-2 tail -- static pairing
// regressed in R11). C-producing CTAs signal a device counter; consumers wait
// only before their gather-add epilogue.
// ---------------------------------------------------------------------------

// ---- staged operands ----
__device__ __align__(1024) __half g_P0[128 * 256];
__device__ __align__(1024) __half g_Pa[2048 * 256];
__device__ __align__(1024) __half g_Pb[8192 * 256];
__device__ __align__(1024) __half g_W[7 * 65536];
__device__ float g_C0[128 * 256];
__device__ float g_C1[2048 * 256];
__device__ int g_done;

// ---------------------------------------------------------------------------
// PTX helpers (baseline sm_90 features only)
// ---------------------------------------------------------------------------
__device__ __forceinline__ uint32_t smem_to_u32(const void* p) {
    uint32_t a;
    asm("{ .reg .u64 t; cvta.to.shared.u64 t, %1; cvt.u32.u64 %0, t; }" : "=r"(a) : "l"(p));
    return a;
}
__device__ __forceinline__ void bulk_cp(uint32_t smem, const void* gmem, uint32_t bytes,
                                        uint32_t mbar) {
    asm volatile(
        "cp.async.bulk.shared::cluster.global.mbarrier::complete_tx::bytes [%0], [%1], %2, [%3];"
        :: "r"(smem), "l"(gmem), "r"(bytes), "r"(mbar) : "memory");
}
#define MBARRIER_INIT(mbar, cnt) \
    asm volatile("mbarrier.init.shared.b64 [%0], %1;" :: "r"((uint32_t)(mbar)), "r"((uint32_t)(cnt)) : "memory")
#define MBARRIER_EXPECT_TX(mbar, tx) \
    asm volatile("mbarrier.arrive.expect_tx.shared.b64 _, [%0], %1;" :: "r"((uint32_t)(mbar)), "r"((uint32_t)(tx)) : "memory")
#define MBARRIER_WAIT_PARITY(mbar, par) do {                                      \
    uint32_t _m = (uint32_t)(mbar); uint32_t _p = (uint32_t)(par); uint32_t _d;   \
    asm volatile("{\n\t.reg .pred p;\n\t"                                         \
        "mbarrier.try_wait.parity.acquire.cta.shared::cta.b64 p, [%1], %2;\n\t"   \
        "selp.b32 %0, 1, 0, p;\n\t}" : "=r"(_d) : "r"(_m), "r"(_p) : "memory");   \
    if (!_d) {                                                                     \
        asm volatile("{\n\t.reg .pred P1;\n\t"                                    \
            "WL_%=:\n\t"                                                          \
            "mbarrier.try_wait.parity.acquire.cta.shared::cta.b64 P1, [%0], %1, 0x989680;\n\t" \
            "@P1 bra.uni WD_%=;\n\t"                                              \
            "bra.uni WL_%=;\n\t"                                                  \
            "WD_%=:\n\t}" :: "r"(_m), "r"(_p) : "memory");                        \
    }                                                                              \
} while (0)

__device__ __forceinline__ void ldsm4(uint32_t* r, uint32_t addr) {
    asm volatile("ldmatrix.sync.aligned.m8n8.x4.shared.b16 {%0,%1,%2,%3}, [%4];"
                 : "=r"(r[0]), "=r"(r[1]), "=r"(r[2]), "=r"(r[3]) : "r"(addr));
}
__device__ __forceinline__ void mma16816(float* d, const uint32_t* a, const uint32_t* b) {
    asm volatile(
        "mma.sync.aligned.m16n8k16.row.col.f32.f16.f16.f32 "
        "{%0,%1,%2,%3}, {%4,%5,%6,%7}, {%8,%9}, {%0,%1,%2,%3};"
        : "+f"(d[0]), "+f"(d[1]), "+f"(d[2]), "+f"(d[3])
        : "r"(a[0]), "r"(a[1]), "r"(a[2]), "r"(a[3]), "r"(b[0]), "r"(b[1]));
}
__device__ __forceinline__ void sts128(uint32_t addr, uint4 v) {
    asm volatile("st.shared.v4.b32 [%0], {%1,%2,%3,%4};"
                 :: "r"(addr), "r"(v.x), "r"(v.y), "r"(v.z), "r"(v.w) : "memory");
}

// slot byte-offset inside a chunk plane for (row r, 16B-slot t)
__device__ __forceinline__ uint32_t plane_off(int r, int t) {
    return (uint32_t)((r >> 1) * 128 + (((((r & 1) << 2) | t) ^ ((r >> 1) & 7)) << 4));
}

// ---------------------------------------------------------------------------
// Prep: pools + fp32->fp16, written chunk-planar pre-swizzled.
// Each thread handles a 64B channel span (two 16B slots) -> 16 independent
// LDG.128 in flight for the f=2 pools (fully unrolled via template F).
// ---------------------------------------------------------------------------
#define S0P (128 * 16)      // P0 slot-pairs
#define S1P (2048 * 16)     // Pa
#define S2P (8192 * 16)     // Pb
#define SWP (7 * 256 * 16)  // weights
#define PREP_PAIRS (S0P + S1P + S2P + SWP)

struct PrepArgs {
    const float* x0; const float* x1; const float* x2;
    const float* w[7];
};

__device__ __forceinline__ uint4 pack8(float4 a, float4 b) {
    __half2 h0 = __floats2half2_rn(a.x, a.y);
    __half2 h1 = __floats2half2_rn(a.z, a.w);
    __half2 h2 = __floats2half2_rn(b.x, b.y);
    __half2 h3 = __floats2half2_rn(b.z, b.w);
    uint4 u;
    u.x = *(uint32_t*)&h0; u.y = *(uint32_t*)&h1;
    u.z = *(uint32_t*)&h2; u.w = *(uint32_t*)&h3;
    return u;
}

template <int F>
__device__ __forceinline__ void prep_pool2(const float* __restrict__ in, __half* dst,
                                           int R, int Hc, int i) {
    const int tp = i & 1;             // t-pair: slots 2tp, 2tp+1
    const int r = (i >> 1) % R;
    const int c = (i >> 1) / R;
    int q = r % Hc;
    int tmp = r / Hc;
    int p = tmp % Hc;
    int b = tmp / Hc;
    const int c16 = c * 8 + tp * 4;   // float4 index base, 4 consecutive (64B)
    const int Win = Hc * F;
    const float4* in4 = (const float4*)in;
    float4 s[4];
#pragma unroll
    for (int j = 0; j < 4; ++j) s[j] = make_float4(0.f, 0.f, 0.f, 0.f);
#pragma unroll
    for (int dy = 0; dy < F; ++dy)
#pragma unroll
        for (int dx = 0; dx < F; ++dx) {
            const float4* pp =
                &in4[(size_t)((b * Hc * F + p * F + dy) * Win + q * F + dx) * 64 + c16];
#pragma unroll
            for (int j = 0; j < 4; ++j) {
                float4 v = pp[j];
                s[j].x += v.x; s[j].y += v.y; s[j].z += v.z; s[j].w += v.w;
            }
        }
    __half* base = dst + (size_t)c * R * 32;
    *(uint4*)(base + (plane_off(r, tp * 2) >> 1)) = pack8(s[0], s[1]);
    *(uint4*)(base + (plane_off(r, tp * 2 + 1) >> 1)) = pack8(s[2], s[3]);
}

__global__ void prep_kernel(PrepArgs pa) {
    if (blockIdx.x == 0 && threadIdx.x == 0) g_done = 0;
    int i = blockIdx.x * blockDim.x + threadIdx.x;
    const int VOFF = 256 * 256;
    if (i < S0P) {
        prep_pool2<4>(pa.x0, g_P0, 128, 4, i);
    } else if ((i -= S0P) < S1P) {
        prep_pool2<2>(pa.x1, g_Pa, 2048, 16, i);
    } else if ((i -= S1P) < S2P) {
        prep_pool2<2>(pa.x2, g_Pb, 8192, 32, i);
    } else if ((i -= S2P) < SWP) {
        const int mat = i >> 12;          // 4096 pairs per matrix
        const int rem = i & 4095;
        const int c = rem >> 9;           // 0..7
        const int r = (rem >> 1) & 255;
        const int tp = rem & 1;
        const float4* src = (const float4*)(pa.w[mat] + VOFF + r * 256 + c * 32 + tp * 16);
        float4 v0 = src[0], v1 = src[1], v2 = src[2], v3 = src[3];
        __half* base = g_W + ((size_t)mat << 16) + (size_t)c * 256 * 32;
        *(uint4*)(base + (plane_off(r, tp * 2) >> 1)) = pack8(v0, v1);
        *(uint4*)(base + (plane_off(r, tp * 2 + 1) >> 1)) = pack8(v2, v3);
    }
}

// ---------------------------------------------------------------------------
// GEMM: BM=128, BN=128, BK=32, 8 warps, 4-stage bulk-copy mbarrier pipeline.
// K=512 jobs: chunks 8..15 take A from fp32 gmem (A2f) via LDG+swizzled STS.
// mode 0: plain; 1: scatter-up by F; 2: gather-add Cadd[coarse(m)].
// dep 0 none; 1 producer (signal g_done); 2 consumer (wait before epilogue).
// ---------------------------------------------------------------------------
struct TCJob {
    const __half *A1, *W1, *W2;
    const float* A2f;
    float* out;
    const float* Cadd;
    int aplane;   // bytes per A chunk plane (= R*64)
    int tile_end, Hc, Wc, F, mode, dep;
};
struct TCJobs { TCJob j[5]; int njobs; int nprod; };

#define STG 16384                  // stage bytes: A 8KB + B 8KB
#define SMEM_TOTAL (4 * STG)       // 65536

__global__ void __launch_bounds__(256, 2)
gemm_tc(TCJobs jobs) {
    extern __shared__ char smem[];
    __shared__ __align__(8) unsigned long long mbars[4];
    const uint32_t sb = smem_to_u32(smem);
    const uint32_t mb = smem_to_u32(mbars);
    const int tid = threadIdx.x;
    const int lid = tid & 31;
    const int wid = tid >> 5;
    const int wm = wid >> 2;       // 0..1
    const int wn = wid & 3;        // 0..3

    const int bt = blockIdx.x;
    int ji = 0;
#pragma unroll
    for (int t = 0; t < 4; ++t)
        if (t + 1 < jobs.njobs && bt >= jobs.j[t].tile_end) ji = t + 1;
    const TCJob jb = jobs.j[ji];
    const int local = bt - (ji == 0 ? 0 : jobs.j[ji - 1].tile_end);
    const int m0 = (local >> 1) * 128;
    const int n0 = (local & 1) * 128;

    const int nch = jb.W2 ? 16 : 8;

    float acc[4][4][4];
#pragma unroll
    for (int a = 0; a < 4; ++a)
#pragma unroll
        for (int b = 0; b < 4; ++b)
#pragma unroll
            for (int c = 0; c < 4; ++c) acc[a][b][c] = 0.f;

    if (tid == 0) {
#pragma unroll
        for (int s = 0; s < 4; ++s) MBARRIER_INIT(mb + 8 * s, 1);
    }
    __syncthreads();

    // issue chunk c into stage c%4 (B always bulk; A bulk only for c<8)
    auto issue = [&](int c) {
        const int s = c & 3;
        const uint32_t stg = sb + s * STG;
        const bool bulkA = (c < 8);
        MBARRIER_EXPECT_TX(mb + 8 * s, bulkA ? 16384u : 8192u);
        const char* wsrc = (const char*)((c < 8) ? jb.W1 : jb.W2) + (c & 7) * 16384 + n0 * 64;
        bulk_cp(stg + 8192, wsrc, 8192, mb + 8 * s);
        if (bulkA) {
            const char* asrc = (const char*)jb.A1 + (size_t)c * jb.aplane + (size_t)m0 * 64;
            bulk_cp(stg, asrc, 8192, mb + 8 * s);
        }
    };

    if (tid == 0) { issue(0); issue(1); issue(2); }

    // A ldmatrix addresses (x4: 16 rows x 16 k)
    const int rA0 = wm * 64 + (lid & 15);
    const int hiA = lid >> 4;
    const uint32_t aBase = (rA0 >> 1) * 128;
    const int xvA = (rA0 >> 1) & 7;
    const int pbA = (rA0 & 1) << 2;
    const uint32_t soA0 = (uint32_t)(((pbA | hiA) ^ xvA) << 4);
    const uint32_t soA1 = (uint32_t)(((pbA | (2 + hiA)) ^ xvA) << 4);

    // B ldmatrix addresses (x4 covering TWO n8 tiles: lanes 16-31 -> rows +8)
    const int rB = wn * 32 + ((lid >> 4) & 1) * 8 + (lid & 7);
    const int hiB = (lid >> 3) & 1;
    const uint32_t bBase = (rB >> 1) * 128;
    const int xvB = (rB >> 1) & 7;
    const int pbB = (rB & 1) << 2;
    const uint32_t soB0 = (uint32_t)(((pbB | hiB) ^ xvB) << 4);
    const uint32_t soB1 = (uint32_t)(((pbB | (2 + hiB)) ^ xvB) << 4);

    // fp32 A path indices (thread covers one row, two 16B slots)
    const int fr = tid >> 1;
    const int ft = (tid & 1) * 2;

    float4 st[4];

#pragma unroll 1
    for (int c = 0; c < nch; ++c) {
        const int s = c & 3;
        MBARRIER_WAIT_PARITY(mb + 8 * s, (c >> 2) & 1);

        const int c3 = c + 3;
        const bool ld2 = (c3 < nch) && (c3 >= 8);
        if (ld2) {
            const float* g = jb.A2f + (size_t)(m0 + fr) * 256 + (c3 & 7) * 32 + ft * 8;
            st[0] = ((const float4*)g)[0];
            st[1] = ((const float4*)g)[1];
            st[2] = ((const float4*)g)[2];
            st[3] = ((const float4*)g)[3];
        }

        const uint32_t sA = sb + s * STG;
        const uint32_t sB = sA + 8192;
#pragma unroll
        for (int ks = 0; ks < 2; ++ks) {
            uint32_t b[4][2];
            const uint32_t so = ks ? soB1 : soB0;
            {
                uint32_t q[4];
                ldsm4(q, sB + bBase + so);          // n-tiles 0,1
                b[0][0] = q[0]; b[0][1] = q[1];
                b[1][0] = q[2]; b[1][1] = q[3];
                ldsm4(q, sB + bBase + 1024 + so);   // n-tiles 2,3 (+16 rows)
                b[2][0] = q[0]; b[2][1] = q[1];
                b[3][0] = q[2]; b[3][1] = q[3];
            }
            const uint32_t sak = ks ? soA1 : soA0;
#pragma unroll
            for (int mi = 0; mi < 4; ++mi) {
                uint32_t a[4];
                ldsm4(a, sA + aBase + mi * 1024 + sak);
#pragma unroll
                for (int ni = 0; ni < 4; ++ni)
                    mma16816(acc[mi][ni], a, b[ni]);
            }
        }

        if (ld2) {
            const uint32_t stg = sb + (c3 & 3) * STG + (fr >> 1) * 128;
            const int pb = (fr & 1) << 2;
            const int xv = (fr >> 1) & 7;
            sts128(stg + (((pb | ft) ^ xv) << 4), pack8(st[0], st[1]));
            sts128(stg + (((pb | (ft + 1)) ^ xv) << 4), pack8(st[2], st[3]));
        }
        __syncthreads();
        if (c3 < nch && tid == 0) issue(c3);
    }

    // Consumers: wait for all C producers before the gather-add epilogue.
    if (jb.dep == 2) {
        if (tid == 0) {
            while (atomicAdd(&g_done, 0) < jobs.nprod) { }
        }
        __syncthreads();
    }

    // Epilogue. D frag: lane holds (row g, col 2tg), (row g+8) pairs.
    const int g = lid >> 2;
    const int tg = lid & 3;
#pragma unroll
    for (int mi = 0; mi < 4; ++mi) {
#pragma unroll
        for (int half = 0; half < 2; ++half) {
            const int rm = m0 + wm * 64 + mi * 16 + g + half * 8;
            if (jb.mode == 0) {
                float* dst = jb.out + (size_t)rm * 256;
#pragma unroll
                for (int ni = 0; ni < 4; ++ni) {
                    const int cn = n0 + wn * 32 + ni * 8 + tg * 2;
                    *(float2*)(dst + cn) = make_float2(acc[mi][ni][half * 2],
                                                       acc[mi][ni][half * 2 + 1]);
                }
            } else if (jb.mode == 1) {
                const int HW = jb.Hc * jb.Wc;
                const int b = rm / HW;
                const int rem = rm - b * HW;
                const int h = rem / jb.Wc;
                const int w = rem - h * jb.Wc;
                const int Wf = jb.Wc * jb.F;
                for (int dy = 0; dy < jb.F; ++dy)
                    for (int dx = 0; dx < jb.F; ++dx) {
                        size_t fm = (size_t)(b * jb.Hc * jb.F + h * jb.F + dy) * Wf
                                    + (w * jb.F + dx);
                        float* dst = jb.out + fm * 256;
#pragma unroll
                        for (int ni = 0; ni < 4; ++ni) {
                            const int cn = n0 + wn * 32 + ni * 8 + tg * 2;
                            *(float2*)(dst + cn) = make_float2(acc[mi][ni][half * 2],
                                                               acc[mi][ni][half * 2 + 1]);
                        }
                    }
            } else {
                const int Wf = jb.Wc * jb.F;
                const int HWf = jb.Hc * jb.F * Wf;
                const int b = rm / HWf;
                const int rem = rm - b * HWf;
                const int h = rem / Wf;
                const int w = rem - h * Wf;
                const int crow = (b * jb.Hc + h / jb.F) * jb.Wc + (w / jb.F);
                const float* csrc = jb.Cadd + (size_t)crow * 256;
                float* dst = jb.out + (size_t)rm * 256;
#pragma unroll
                for (int ni = 0; ni < 4; ++ni) {
                    const int cn = n0 + wn * 32 + ni * 8 + tg * 2;
                    float2 cv = *(const float2*)(csrc + cn);
                    *(float2*)(dst + cn) = make_float2(acc[mi][ni][half * 2] + cv.x,
                                                       acc[mi][ni][half * 2 + 1] + cv.y);
                }
            }
        }
    }

    // Producers: make C visible, then signal.
    if (jb.dep == 1) {
        __threadfence();
        __syncthreads();
        if (tid == 0) atomicAdd(&g_done, 1);
    }
}

// ---------------------------------------------------------------------------
// Launch
// ---------------------------------------------------------------------------
extern "C" void kernel_launch(void* const* d_in, const int* in_sizes, int n_in,
                              void* d_out, int out_size) {
    (void)n_in; (void)out_size;

    const float* x0 = (const float*)d_in[0];   // [8,16,16,256]
    const float* x1 = (const float*)d_in[1];   // [8,32,32,256]
    const float* x2 = (const float*)d_in[2];   // [8,64,64,256]

    // setup_inputs() builds the dict INTERLEAVED (qpeer_w0, kvpeer_w0, ...).
    const bool inter = (in_sizes[4] == 2 * 256 * 256);
    const float* kvpeer0 = (const float*)d_in[inter ? 4  : 6];
    const float* kvpeer1 = (const float*)d_in[inter ? 6  : 7];
    const float* kvpeer2 = (const float*)d_in[inter ? 8  : 8];
    const float* kvpar1  = (const float*)d_in[inter ? 10 : 11];
    const float* kvpar2  = (const float*)d_in[inter ? 12 : 12];
    const float* kvkid0  = (const float*)d_in[inter ? 14 : 15];
    const float* kvkid1  = (const float*)d_in[inter ? 16 : 16];

    __half *P0, *Pa, *Pb, *W;
    float *C0, *C1;
    cudaGetSymbolAddress((void**)&P0, g_P0);
    cudaGetSymbolAddress((void**)&Pa, g_Pa);
    cudaGetSymbolAddress((void**)&Pb, g_Pb);
    cudaGetSymbolAddress((void**)&W, g_W);
    cudaGetSymbolAddress((void**)&C0, g_C0);
    cudaGetSymbolAddress((void**)&C1, g_C1);

    float* out0 = (float*)d_out;                 // 8*16*16*256
    float* out1 = out0 + 8 * 16 * 16 * 256;      // 8*32*32*256
    float* out2 = out1 + 8 * 32 * 32 * 256;      // 8*64*64*256

    cudaFuncSetAttribute(gemm_tc, cudaFuncAttributeMaxDynamicSharedMemorySize, SMEM_TOTAL);

    // 1) prep (also resets g_done)
    PrepArgs pa;
    pa.x0 = x0; pa.x1 = x1; pa.x2 = x2;
    pa.w[0] = kvpeer0; pa.w[1] = kvpeer1; pa.w[2] = kvpeer2;
    pa.w[3] = kvpar1;  pa.w[4] = kvpar2;  pa.w[5] = kvkid0;  pa.w[6] = kvkid1;
    prep_kernel<<<(PREP_PAIRS + 255) / 256, 256>>>(pa);

    __half* W0 = W;             // peer0
    __half* W1 = W + 65536;     // peer1
    __half* W2 = W + 131072;    // peer2
    __half* W3 = W + 196608;    // par1
    __half* W4 = W + 262144;    // par2
    __half* W5 = W + 327680;    // kid0
    __half* W6 = W + 393216;    // kid1

    // 2) single merged GEMM launch (producers first: blocks 0..33)
    TCJobs tj;
    tj.njobs = 5;
    tj.nprod = 34;
    //        A1  W1  W2      A2f  out   Cadd    aplane    end  Hc  Wc F  mode dep
    tj.j[0] = { P0, W0, nullptr, nullptr, C0,   nullptr, 128 * 64,  2,   0,  0, 0, 0, 1 };
    tj.j[1] = { Pa, W1, W3,      x0,      C1,   nullptr, 2048 * 64, 34,  0,  0, 0, 0, 1 };
    tj.j[2] = { Pb, W2, W4,      x1,      out2, nullptr, 8192 * 64, 162, 32, 32, 2, 1, 0 };
    tj.j[3] = { Pa, W5, nullptr, nullptr, out0, C0,      2048 * 64, 194, 4,  4,  4, 2, 2 };
    tj.j[4] = { Pb, W6, nullptr, nullptr, out1, C1,      8192 * 64, 322, 16, 16, 2, 2, 2 };
    gemm_tc<<<322, 256, SMEM_TOTAL>>>(tj);
}